// round 8
// baseline (speedup 1.0000x reference)
#include <cuda_runtime.h>
#include <cuda_fp16.h>
#include <cstdint>

#define NPTS  2000000
#define TILES 15625          // 2,000,000 / 128 exactly

// dynamic shared layout (bytes) — 45,440 total -> 5 CTAs/SM
#define XS_OFF  0            // half [128][72]  stride 144B (16r%128 distinct -> LDSM ok)
#define W1A_OFF 18432        // half [64][72]   phase-A cols (perm'd k 0..63)
#define W1B_OFF 27648        // half [64][56]   stride 112B, phase-B cols (48 used)
#define W2_OFF  34816        // half [64][72]
#define W3_OFF  44032        // half [8][72]
#define B1P_OFF 45184        // uint32 [32] packed bias pairs (nt*4+tig)
#define B2P_OFF 45312        // uint32 [32]
#define SMEM_BYTES 45440

__device__ __forceinline__ uint32_t pk(float a, float b) {
    __half2 h = __floats2half2_rn(a, b);
    return *reinterpret_cast<uint32_t*>(&h);
}

__device__ __forceinline__ float2 upk(uint32_t v) {
    __half2 h = *reinterpret_cast<__half2*>(&v);
    return __half22float2(h);
}

__device__ __forceinline__ void sts8(__half* p,
    float a, float b, float c, float d, float e, float f, float g, float h) {
    uint4 u;
    u.x = pk(a, b); u.y = pk(c, d); u.z = pk(e, f); u.w = pk(g, h);
    *reinterpret_cast<uint4*>(p) = u;
}

// f16 accumulate
__device__ __forceinline__ void mma16816h(uint32_t* c,
    const uint32_t* a, uint32_t b0, uint32_t b1) {
    asm volatile(
        "mma.sync.aligned.m16n8k16.row.col.f16.f16.f16.f16 "
        "{%0,%1}, {%2,%3,%4,%5}, {%6,%7}, {%0,%1};\n"
        : "+r"(c[0]), "+r"(c[1])
        : "r"(a[0]), "r"(a[1]), "r"(a[2]), "r"(a[3]), "r"(b0), "r"(b1));
}

// f32 accumulate (layer 3)
__device__ __forceinline__ void mma16816f(float* c,
    const uint32_t* a, uint32_t b0, uint32_t b1) {
    asm volatile(
        "mma.sync.aligned.m16n8k16.row.col.f32.f16.f16.f32 "
        "{%0,%1,%2,%3}, {%4,%5,%6,%7}, {%8,%9}, {%0,%1,%2,%3};\n"
        : "+f"(c[0]), "+f"(c[1]), "+f"(c[2]), "+f"(c[3])
        : "r"(a[0]), "r"(a[1]), "r"(a[2]), "r"(a[3]), "r"(b0), "r"(b1));
}

__device__ __forceinline__ void ldsm4(uint32_t* r, uint32_t addr) {
    asm volatile(
        "ldmatrix.sync.aligned.m8n8.x4.shared.b16 {%0,%1,%2,%3}, [%4];\n"
        : "=r"(r[0]), "=r"(r[1]), "=r"(r[2]), "=r"(r[3]) : "r"(addr));
}

__global__ void __launch_bounds__(128, 5)
fused_encode_mlp(const float* __restrict__ bases,
                 const float* __restrict__ normals,
                 const float* __restrict__ enc,
                 const float* __restrict__ W1, const float* __restrict__ b1,
                 const float* __restrict__ W2, const float* __restrict__ b2,
                 const float* __restrict__ W3, const float* __restrict__ b3,
                 float* __restrict__ out)
{
    extern __shared__ char smem[];
    __half* XS   = reinterpret_cast<__half*>(smem + XS_OFF);
    __half* W1A  = reinterpret_cast<__half*>(smem + W1A_OFF);
    __half* W1B  = reinterpret_cast<__half*>(smem + W1B_OFF);
    __half* W2S  = reinterpret_cast<__half*>(smem + W2_OFF);
    __half* W3hS = reinterpret_cast<__half*>(smem + W3_OFF);
    uint32_t* B1P = reinterpret_cast<uint32_t*>(smem + B1P_OFF);
    uint32_t* B2P = reinterpret_cast<uint32_t*>(smem + B2P_OFF);

    const int tid  = threadIdx.x;
    const int lane = tid & 31;
    const int wp   = tid >> 5;
    const int g    = lane >> 2;
    const int tig  = lane & 3;
    const int warpRow = wp * 32;

    // ---- stage weights once per CTA (zero pads first) ----
    for (int i = tid; i < (B1P_OFF - W1A_OFF) / 4; i += 128)
        reinterpret_cast<uint32_t*>(smem + W1A_OFF)[i] = 0;
    __syncthreads();
    // W1A: phase-A columns with permutation (59<-orig71 n0, 60<-orig72 n1, 61..63<-orig59..61 sn6)
    for (int i = tid; i < 64 * 64; i += 128) {
        int k = i >> 6, j = i & 63;
        int ko = (k < 59) ? k : (k == 59) ? 71 : (k == 60) ? 72 : (k - 2);
        W1A[j * 72 + k] = __float2half(W1[ko * 64 + j]);
    }
    // W1B: phase-B columns: s<9 -> orig 62+s (cs6, level7), else orig 64+s (blobs)
    for (int i = tid; i < 41 * 64; i += 128) {
        int s = i >> 6, j = i & 63;
        int ko = (s < 9) ? (62 + s) : (64 + s);
        W1B[j * 56 + s] = __float2half(W1[ko * 64 + j]);
    }
    for (int i = tid; i < 64 * 64; i += 128) {
        int k = i >> 6, j = i & 63;
        W2S[j * 72 + k] = __float2half(W2[i]);
    }
    if (tid < 64) {
        int k = tid;
        W3hS[0 * 72 + k] = __float2half(W3[k * 3 + 0]);
        W3hS[1 * 72 + k] = __float2half(W3[k * 3 + 1]);
        W3hS[2 * 72 + k] = __float2half(W3[k * 3 + 2]);
    }
    if (tid < 32) {   // packed bias pairs: index = nt*4 + tig
        int nt = tid >> 2, tg = tid & 3;
        B1P[tid] = pk(b1[nt * 8 + tg * 2], b1[nt * 8 + tg * 2 + 1]);
        B2P[tid] = pk(b2[nt * 8 + tg * 2], b2[nt * 8 + tg * 2 + 1]);
    }
    __syncthreads();

    // ---- ldmatrix addresses ----
    const uint32_t xs_b  = (uint32_t)__cvta_generic_to_shared(XS);
    const uint32_t w1a_b = (uint32_t)__cvta_generic_to_shared(W1A);
    const uint32_t w1b_b = (uint32_t)__cvta_generic_to_shared(W1B);
    const uint32_t w2_b  = (uint32_t)__cvta_generic_to_shared(W2S);
    const uint32_t w3_b  = (uint32_t)__cvta_generic_to_shared(W3hS);

    const int aRowIn = (lane & 7) + ((lane >> 3) & 1) * 8;
    const int aCol   = ((lane >> 4) & 1) * 16;
    uint32_t baseA0 = xs_b + (uint32_t)((warpRow + aRowIn) * 144 + aCol);
    uint32_t baseA1 = baseA0 + 16u * 144u;

    const int bRowIn = (lane & 7) + ((lane >> 4) & 1) * 8;
    const int bCol   = ((lane >> 3) & 1) * 16;
    const uint32_t bB1a = w1a_b + (uint32_t)(bRowIn * 144 + bCol);
    const uint32_t bB1b = w1b_b + (uint32_t)(bRowIn * 112 + bCol);
    const uint32_t bB2  = w2_b  + (uint32_t)(bRowIn * 144 + bCol);
    const uint32_t bB3  = w3_b  + (uint32_t)((lane & 7) * 144 + bCol);

    const float i3a = (tig == 0) ? b3[0] : (tig == 1) ? b3[2] : 0.f;
    const float i3b = (tig == 0) ? b3[1] : 0.f;

    for (int tile = blockIdx.x; tile < TILES; tile += gridDim.x) {
        const int row = tile * 128 + tid;
        __half* xr = XS + tid * 72;

        // ================= phase A features: cols 0..63 =================
        {
            const float4* ep = reinterpret_cast<const float4*>(enc + (size_t)row * 20);
            float4 e0 = ep[0], e1 = ep[1];
            sts8(xr + 0, e0.x, e0.y, e0.z, e0.w, e1.x, e1.y, e1.z, e1.w);
            float4 e2 = ep[2], e3 = ep[3];
            sts8(xr + 8, e2.x, e2.y, e2.z, e2.w, e3.x, e3.y, e3.z, e3.w);
            float4 e4v = ep[4];
            float bx0 = bases[row * 3 + 0], by0 = bases[row * 3 + 1], bz0 = bases[row * 3 + 2];

            float s0x, s0y, s0z, c0x, c0y, c0z;
            __sincosf(2.f * bx0, &s0x, &c0x);
            __sincosf(2.f * by0, &s0y, &c0y);
            __sincosf(2.f * bz0, &s0z, &c0z);
            sts8(xr + 16, e4v.x, e4v.y, e4v.z, e4v.w, bx0, by0, bz0, s0x);

            // rolling double-angle: (s,c) level i -> i+1 ; interleave stores to cap liveness
            float s1x = 2.f*s0x*c0x, c1x = 1.f-2.f*s0x*s0x;
            float s1y = 2.f*s0y*c0y, c1y = 1.f-2.f*s0y*s0y;
            float s1z = 2.f*s0z*c0z, c1z = 1.f-2.f*s0z*s0z;
            sts8(xr + 24, s0y, s0z, c0x, c0y, c0z, s1x, s1y, s1z);

            float s2x = 2.f*s1x*c1x, c2x = 1.f-2.f*s1x*s1x;
            float s2y = 2.f*s1y*c1y, c2y = 1.f-2.f*s1y*s1y;
            float s2z = 2.f*s1z*c1z, c2z = 1.f-2.f*s1z*s1z;
            sts8(xr + 32, c1x, c1y, c1z, s2x, s2y, s2z, c2x, c2y);

            float s3x = 2.f*s2x*c2x, c3x = 1.f-2.f*s2x*s2x;
            float s3y = 2.f*s2y*c2y, c3y = 1.f-2.f*s2y*s2y;
            float s3z = 2.f*s2z*c2z, c3z = 1.f-2.f*s2z*s2z;
            float s4x = 2.f*s3x*c3x, c4x = 1.f-2.f*s3x*s3x;
            sts8(xr + 40, c2z, s3x, s3y, s3z, c3x, c3y, c3z, s4x);

            float s4y = 2.f*s3y*c3y, c4y = 1.f-2.f*s3y*s3y;
            float s4z = 2.f*s3z*c3z, c4z = 1.f-2.f*s3z*s3z;
            float s5x = 2.f*s4x*c4x, c5x = 1.f-2.f*s4x*s4x;
            float s5y = 2.f*s4y*c4y, c5y = 1.f-2.f*s4y*s4y;
            float s5z = 2.f*s4z*c4z, c5z = 1.f-2.f*s4z*s4z;
            sts8(xr + 48, s4y, s4z, c4x, c4y, c4z, s5x, s5y, s5z);

            float n0 = normals[row * 2 + 0], n1 = normals[row * 2 + 1];
            float s6x = 2.f*s5x*c5x, c6x = 1.f-2.f*s5x*s5x;
            float s6y = 2.f*s5y*c5y, c6y = 1.f-2.f*s5y*s5y;
            float s6z = 2.f*s5z*c5z, c6z = 1.f-2.f*s5z*s5z;
            sts8(xr + 56, c5x, c5y, c5z, n0, n1, s6x, s6y, s6z);

            __syncwarp();

            // ======== layer 1, phase A: kk = 0..3 ========
            uint32_t acc[2][8][2];
            #pragma unroll
            for (int nt = 0; nt < 8; nt++) {
                uint32_t bw = B1P[nt * 4 + tig];
                acc[0][nt][0] = bw; acc[0][nt][1] = bw;
                acc[1][nt][0] = bw; acc[1][nt][1] = bw;
            }
            #pragma unroll
            for (int kk = 0; kk < 4; kk++) {
                uint32_t aA[4], aB[4];
                ldsm4(aA, baseA0 + kk * 32);
                ldsm4(aB, baseA1 + kk * 32);
                #pragma unroll
                for (int p = 0; p < 4; p++) {
                    uint32_t b[4];
                    ldsm4(b, bB1a + p * (16 * 144) + kk * 32);
                    mma16816h(acc[0][2 * p],     aA, b[0], b[1]);
                    mma16816h(acc[0][2 * p + 1], aA, b[2], b[3]);
                    mma16816h(acc[1][2 * p],     aB, b[0], b[1]);
                    mma16816h(acc[1][2 * p + 1], aB, b[2], b[3]);
                }
            }
            __syncwarp();   // all LDSM of phase-A X done before overwrite

            // ================= phase B features: 48 cols into XS 0..47 =================
            float s7x = 2.f*s6x*c6x, c7x = 1.f-2.f*s6x*s6x;
            float s7y = 2.f*s6y*c6y, c7y = 1.f-2.f*s6y*s6y;
            float s7z = 2.f*s6z*c6z, c7z = 1.f-2.f*s6z*s6z;
            sts8(xr + 0, c6x, c6y, c6z, s7x, s7y, s7z, c7x, c7y);

            const float V1 = 0.80073740291680f;   // exp(-50/225)
            const float V2 = 0.64118038843357f;   // exp(-100/225)
            {
                float E = __expf(-50.f * n0 * n0);
                float r = __expf(6.66666667f * n0) * V1;
                float t1=E;  E*=r; r*=V2; float t2=E; E*=r; r*=V2;
                float t3=E;  E*=r; r*=V2; float t4=E; E*=r; r*=V2;
                float t5=E;  E*=r; r*=V2; float t6=E; E*=r; r*=V2;
                sts8(xr + 8, c7z, t1, t2, t3, t4, t5, t6, E);
                E*=r; r*=V2; t1=E; E*=r; r*=V2; t2=E; E*=r; r*=V2;
                t3=E; E*=r; r*=V2; t4=E; E*=r; r*=V2; t5=E; E*=r; r*=V2;
                t6=E; E*=r; r*=V2; float t7=E; E*=r; r*=V2;
                sts8(xr + 16, t1, t2, t3, t4, t5, t6, t7, E);
                E *= r;   // bl0[15]
                float F = __expf(-50.f * n1 * n1);
                float q = __expf(6.66666667f * n1) * V1;
                t1=F; F*=q; q*=V2; t2=F; F*=q; q*=V2; t3=F; F*=q; q*=V2;
                t4=F; F*=q; q*=V2; t5=F; F*=q; q*=V2; t6=F; F*=q; q*=V2;
                t7=F; F*=q; q*=V2;
                sts8(xr + 24, E, t1, t2, t3, t4, t5, t6, t7);
                t1=F; F*=q; q*=V2; t2=F; F*=q; q*=V2; t3=F; F*=q; q*=V2;
                t4=F; F*=q; q*=V2; t5=F; F*=q; q*=V2; t6=F; F*=q; q*=V2;
                t7=F; F*=q; q*=V2; float t8=F; F*=q;
                sts8(xr + 32, t1, t2, t3, t4, t5, t6, t7, t8);
                sts8(xr + 40, F, 0.f, 0.f, 0.f, 0.f, 0.f, 0.f, 0.f);
            }
            __syncwarp();

            // ======== layer 1, phase B: kk = 0..2 (48 cols) ========
            #pragma unroll
            for (int kk = 0; kk < 3; kk++) {
                uint32_t aA[4], aB[4];
                ldsm4(aA, baseA0 + kk * 32);
                ldsm4(aB, baseA1 + kk * 32);
                #pragma unroll
                for (int p = 0; p < 4; p++) {
                    uint32_t b[4];
                    ldsm4(b, bB1b + p * (16 * 112) + kk * 32);
                    mma16816h(acc[0][2 * p],     aA, b[0], b[1]);
                    mma16816h(acc[0][2 * p + 1], aA, b[2], b[3]);
                    mma16816h(acc[1][2 * p],     aB, b[0], b[1]);
                    mma16816h(acc[1][2 * p + 1], aB, b[2], b[3]);
                }
            }

            // sin + repack in place
            #pragma unroll
            for (int mt = 0; mt < 2; mt++)
                #pragma unroll
                for (int nt = 0; nt < 8; nt++) {
                    float2 zlo = upk(acc[mt][nt][0]);
                    float2 zhi = upk(acc[mt][nt][1]);
                    acc[mt][nt][0] = pk(__sinf(zlo.x), __sinf(zlo.y));
                    acc[mt][nt][1] = pk(__sinf(zhi.x), __sinf(zhi.y));
                }

            // ======== layer 2 ========
            uint32_t ac2[2][8][2];
            #pragma unroll
            for (int nt = 0; nt < 8; nt++) {
                uint32_t bw = B2P[nt * 4 + tig];
                ac2[0][nt][0] = bw; ac2[0][nt][1] = bw;
                ac2[1][nt][0] = bw; ac2[1][nt][1] = bw;
            }
            #pragma unroll
            for (int kk = 0; kk < 4; kk++) {
                #pragma unroll
                for (int p = 0; p < 4; p++) {
                    uint32_t b[4];
                    ldsm4(b, bB2 + p * (16 * 144) + kk * 32);
                    #pragma unroll
                    for (int mt = 0; mt < 2; mt++) {
                        uint32_t a[4] = { acc[mt][2 * kk][0], acc[mt][2 * kk][1],
                                          acc[mt][2 * kk + 1][0], acc[mt][2 * kk + 1][1] };
                        mma16816h(ac2[mt][2 * p],     a, b[0], b[1]);
                        mma16816h(ac2[mt][2 * p + 1], a, b[2], b[3]);
                    }
                }
            }

            // sin + repack act2 in place
            #pragma unroll
            for (int mt = 0; mt < 2; mt++)
                #pragma unroll
                for (int nt = 0; nt < 8; nt++) {
                    float2 zlo = upk(ac2[mt][nt][0]);
                    float2 zhi = upk(ac2[mt][nt][1]);
                    ac2[mt][nt][0] = pk(__sinf(zlo.x), __sinf(zlo.y));
                    ac2[mt][nt][1] = pk(__sinf(zhi.x), __sinf(zhi.y));
                }

            // ======== layer 3 via MMA (N=8 pad, f32 acc) ========
            #pragma unroll
            for (int mt = 0; mt < 2; mt++) {
                float c[4] = { i3a, i3b, i3a, i3b };
                #pragma unroll
                for (int kk = 0; kk < 4; kk++) {
                    uint32_t t[4];
                    ldsm4(t, bB3 + kk * 32);
                    uint32_t a[4] = { ac2[mt][2 * kk][0], ac2[mt][2 * kk][1],
                                      ac2[mt][2 * kk + 1][0], ac2[mt][2 * kk + 1][1] };
                    mma16816f(c, a, t[0], t[1]);
                }

                float bxA = __shfl_sync(0xffffffffu, bx0, mt * 16 + g);
                float byA = __shfl_sync(0xffffffffu, by0, mt * 16 + g);
                float bzA = __shfl_sync(0xffffffffu, bz0, mt * 16 + g);
                float bxB = __shfl_sync(0xffffffffu, bx0, mt * 16 + g + 8);
                float byB = __shfl_sync(0xffffffffu, by0, mt * 16 + g + 8);
                float bzB = __shfl_sync(0xffffffffu, bz0, mt * 16 + g + 8);

                int rA = tile * 128 + warpRow + mt * 16 + g;
                int rB = rA + 8;
                if (tig == 0) {
                    out[rA * 3 + 0] = bxA + c[0];
                    out[rA * 3 + 1] = byA + c[1];
                    out[rB * 3 + 0] = bxB + c[2];
                    out[rB * 3 + 1] = byB + c[3];
                } else if (tig == 1) {
                    out[rA * 3 + 2] = bzA + c[0];
                    out[rB * 3 + 2] = bzB + c[2];
                }
            }
        }
        __syncwarp();   // XS reads done before next tile's phase A overwrites
    }
}

extern "C" void kernel_launch(void* const* d_in, const int* in_sizes, int n_in,
                              void* d_out, int out_size) {
    const float* bases   = (const float*)d_in[0];
    const float* normals = (const float*)d_in[1];
    const float* enc     = (const float*)d_in[2];
    const float* W1      = (const float*)d_in[3];
    const float* b1      = (const float*)d_in[4];
    const float* W2      = (const float*)d_in[5];
    const float* b2      = (const float*)d_in[6];
    const float* W3      = (const float*)d_in[7];
    const float* b3      = (const float*)d_in[8];
    float* out = (float*)d_out;

    cudaFuncSetAttribute(fused_encode_mlp,
                         cudaFuncAttributeMaxDynamicSharedMemorySize, SMEM_BYTES);

    // persistent: 148 SMs x 5 CTAs (45.4 KB smem each, 20 warps/SM)
    fused_encode_mlp<<<740, 128, SMEM_BYTES>>>(bases, normals, enc,
                                               W1, b1, W2, b2, W3, b3, out);
}

// round 9
// speedup vs baseline: 1.0109x; 1.0109x over previous
#include <cuda_runtime.h>
#include <cuda_fp16.h>
#include <cstdint>

#define NPTS  2000000
#define TILES 15625          // 2,000,000 / 128 exactly

// dynamic shared layout (bytes)
#define XS_OFF 0             // half [128][120]  (stride 240B, LDSM conflict-free)
#define W1_OFF 30720         // half [64][120]   W1S[j][k] = W1[k][j], k pad 105->112 zeros
#define W2_OFF 46080         // half [64][72]    W2S[j][k] = W2[k][j]
#define W3_OFF 55296         // half [8][72]     W3hS[n][k] = W3[k*3+n] (n<3), else 0
#define B1_OFF 56448         // float [64]
#define B2_OFF 56704         // float [64]
#define SMEM_BYTES 56960

__device__ __forceinline__ uint32_t pk(float a, float b) {
    __half2 h = __floats2half2_rn(a, b);
    return *reinterpret_cast<uint32_t*>(&h);
}

__device__ __forceinline__ void sts8(__half* p,
    float a, float b, float c, float d, float e, float f, float g, float h) {
    uint4 u;
    u.x = pk(a, b); u.y = pk(c, d); u.z = pk(e, f); u.w = pk(g, h);
    *reinterpret_cast<uint4*>(p) = u;
}

// f32 accumulate
__device__ __forceinline__ void mma16816f(float* c,
    const uint32_t* a, uint32_t b0, uint32_t b1) {
    asm volatile(
        "mma.sync.aligned.m16n8k16.row.col.f32.f16.f16.f32 "
        "{%0,%1,%2,%3}, {%4,%5,%6,%7}, {%8,%9}, {%0,%1,%2,%3};\n"
        : "+f"(c[0]), "+f"(c[1]), "+f"(c[2]), "+f"(c[3])
        : "r"(a[0]), "r"(a[1]), "r"(a[2]), "r"(a[3]), "r"(b0), "r"(b1));
}

__device__ __forceinline__ void ldsm4(uint32_t* r, uint32_t addr) {
    asm volatile(
        "ldmatrix.sync.aligned.m8n8.x4.shared.b16 {%0,%1,%2,%3}, [%4];\n"
        : "=r"(r[0]), "=r"(r[1]), "=r"(r[2]), "=r"(r[3]) : "r"(addr));
}

__global__ void __launch_bounds__(128, 4)
fused_encode_mlp(const float* __restrict__ bases,
                 const float* __restrict__ normals,
                 const float* __restrict__ enc,
                 const float* __restrict__ W1, const float* __restrict__ b1,
                 const float* __restrict__ W2, const float* __restrict__ b2,
                 const float* __restrict__ W3, const float* __restrict__ b3,
                 float* __restrict__ out)
{
    extern __shared__ char smem[];
    __half* XS   = reinterpret_cast<__half*>(smem + XS_OFF);
    __half* W1S  = reinterpret_cast<__half*>(smem + W1_OFF);
    __half* W2S  = reinterpret_cast<__half*>(smem + W2_OFF);
    __half* W3hS = reinterpret_cast<__half*>(smem + W3_OFF);
    float*  B1S  = reinterpret_cast<float*>(smem + B1_OFF);
    float*  B2S  = reinterpret_cast<float*>(smem + B2_OFF);

    const int tid  = threadIdx.x;
    const int lane = tid & 31;
    const int wp   = tid >> 5;
    const int g    = lane >> 2;
    const int tig  = lane & 3;
    const int warpRow = wp * 32;

    // ---- stage weights once per CTA ----
    for (int i = tid; i < 64 * 120; i += 128) W1S[i] = __float2half(0.f);
    for (int i = tid; i < 8 * 72; i += 128)   W3hS[i] = __float2half(0.f);
    __syncthreads();
    for (int i = tid; i < 105 * 64; i += 128) {
        int k = i >> 6, j = i & 63;
        W1S[j * 120 + k] = __float2half(W1[i]);
    }
    for (int i = tid; i < 64 * 64; i += 128) {
        int k = i >> 6, j = i & 63;
        W2S[j * 72 + k] = __float2half(W2[i]);
    }
    if (tid < 64) {
        int k = tid;
        W3hS[0 * 72 + k] = __float2half(W3[k * 3 + 0]);
        W3hS[1 * 72 + k] = __float2half(W3[k * 3 + 1]);
        W3hS[2 * 72 + k] = __float2half(W3[k * 3 + 2]);
        B1S[k] = b1[k];
        B2S[k] = b2[k];
    }
    __syncthreads();

    // ---- ldmatrix addresses ----
    const uint32_t xs_b = (uint32_t)__cvta_generic_to_shared(XS);
    const uint32_t w1_b = (uint32_t)__cvta_generic_to_shared(W1S);
    const uint32_t w2_b = (uint32_t)__cvta_generic_to_shared(W2S);
    const uint32_t w3_b = (uint32_t)__cvta_generic_to_shared(W3hS);

    const int aRowIn = (lane & 7) + ((lane >> 3) & 1) * 8;
    const int aCol   = ((lane >> 4) & 1) * 16;
    uint32_t baseA0 = xs_b + (uint32_t)((warpRow + aRowIn) * 240 + aCol);
    uint32_t baseA1 = baseA0 + 16u * 240u;

    const int bRowIn = (lane & 7) + ((lane >> 4) & 1) * 8;
    const int bCol   = ((lane >> 3) & 1) * 16;
    uint32_t baseB1[4], baseB2[4];
    #pragma unroll
    for (int p = 0; p < 4; p++) {
        baseB1[p] = w1_b + (uint32_t)((p * 16 + bRowIn) * 240 + bCol);
        baseB2[p] = w2_b + (uint32_t)((p * 16 + bRowIn) * 144 + bCol);
    }

    // ---- hoist W3 B-fragments (N=8 tile; 8 regs) ----
    uint32_t B3f[4][2];
    {
        uint32_t baseB3 = w3_b + (uint32_t)((lane & 7) * 144 + bCol);
        #pragma unroll
        for (int kk = 0; kk < 4; kk++) {
            uint32_t t[4];
            ldsm4(t, baseB3 + kk * 32);
            B3f[kk][0] = t[0]; B3f[kk][1] = t[1];
        }
    }

    const float i3a = (tig == 0) ? b3[0] : (tig == 1) ? b3[2] : 0.f;   // C col 2*tig
    const float i3b = (tig == 0) ? b3[1] : 0.f;                        // C col 2*tig+1

    for (int tile = blockIdx.x; tile < TILES; tile += gridDim.x) {
        const int row = tile * 128 + tid;

        // ================= features -> SMEM (fp16, cols 0..111) =================
        __half* xr = XS + tid * 120;

        const float4* ep = reinterpret_cast<const float4*>(enc + (size_t)row * 20);
        float4 e0 = ep[0], e1 = ep[1], e2 = ep[2], e3 = ep[3], e4v = ep[4];
        sts8(xr + 0, e0.x, e0.y, e0.z, e0.w, e1.x, e1.y, e1.z, e1.w);
        sts8(xr + 8, e2.x, e2.y, e2.z, e2.w, e3.x, e3.y, e3.z, e3.w);

        float bx = bases[row * 3 + 0], by = bases[row * 3 + 1], bz = bases[row * 3 + 2];

        float sn[8][3], cs[8][3];
        __sincosf(2.f * bx, &sn[0][0], &cs[0][0]);
        __sincosf(2.f * by, &sn[0][1], &cs[0][1]);
        __sincosf(2.f * bz, &sn[0][2], &cs[0][2]);
        #pragma unroll
        for (int i = 1; i < 8; i++) {
            #pragma unroll
            for (int d = 0; d < 3; d++) {
                float s = sn[i - 1][d], c = cs[i - 1][d];
                sn[i][d] = 2.f * s * c;
                cs[i][d] = 1.f - 2.f * s * s;
            }
        }
        sts8(xr + 16, e4v.x, e4v.y, e4v.z, e4v.w, bx, by, bz, sn[0][0]);
        sts8(xr + 24, sn[0][1], sn[0][2], cs[0][0], cs[0][1], cs[0][2], sn[1][0], sn[1][1], sn[1][2]);
        sts8(xr + 32, cs[1][0], cs[1][1], cs[1][2], sn[2][0], sn[2][1], sn[2][2], cs[2][0], cs[2][1]);
        sts8(xr + 40, cs[2][2], sn[3][0], sn[3][1], sn[3][2], cs[3][0], cs[3][1], cs[3][2], sn[4][0]);
        sts8(xr + 48, sn[4][1], sn[4][2], cs[4][0], cs[4][1], cs[4][2], sn[5][0], sn[5][1], sn[5][2]);
        sts8(xr + 56, cs[5][0], cs[5][1], cs[5][2], sn[6][0], sn[6][1], sn[6][2], cs[6][0], cs[6][1]);

        float n0 = normals[row * 2 + 0], n1 = normals[row * 2 + 1];
        sts8(xr + 64, cs[6][2], sn[7][0], sn[7][1], sn[7][2], cs[7][0], cs[7][1], cs[7][2], n0);

        float bl0[16], bl1[16];
        {
            const float V1 = 0.80073740291680f;   // exp(-50/225)
            const float V2 = 0.64118038843357f;   // exp(-100/225)
            float E0 = __expf(-50.f * n0 * n0);
            float r0 = __expf(6.66666667f * n0) * V1;
            float E1 = __expf(-50.f * n1 * n1);
            float r1 = __expf(6.66666667f * n1) * V1;
            bl0[0] = E0; bl1[0] = E1;
            #pragma unroll
            for (int k = 1; k < 16; k++) {
                E0 *= r0; r0 *= V2; bl0[k] = E0;
                E1 *= r1; r1 *= V2; bl1[k] = E1;
            }
        }
        sts8(xr + 72,  n1, bl0[0], bl0[1], bl0[2], bl0[3], bl0[4], bl0[5], bl0[6]);
        sts8(xr + 80,  bl0[7], bl0[8], bl0[9], bl0[10], bl0[11], bl0[12], bl0[13], bl0[14]);
        sts8(xr + 88,  bl0[15], bl1[0], bl1[1], bl1[2], bl1[3], bl1[4], bl1[5], bl1[6]);
        sts8(xr + 96,  bl1[7], bl1[8], bl1[9], bl1[10], bl1[11], bl1[12], bl1[13], bl1[14]);
        sts8(xr + 104, bl1[15], 0.f, 0.f, 0.f, 0.f, 0.f, 0.f, 0.f);

        __syncwarp();   // warp reads only its own 32 rows

        // ================= layer 1: f32 accumulators, bias-initialized =================
        float acc[2][8][4];
        #pragma unroll
        for (int nt = 0; nt < 8; nt++) {
            float bv0 = B1S[nt * 8 + tig * 2];
            float bv1 = B1S[nt * 8 + tig * 2 + 1];
            #pragma unroll
            for (int mt = 0; mt < 2; mt++) {
                acc[mt][nt][0] = bv0; acc[mt][nt][1] = bv1;
                acc[mt][nt][2] = bv0; acc[mt][nt][3] = bv1;
            }
        }

        #pragma unroll
        for (int kk = 0; kk < 7; kk++) {
            uint32_t aA[4], aB[4];
            ldsm4(aA, baseA0 + kk * 32);
            ldsm4(aB, baseA1 + kk * 32);
            #pragma unroll
            for (int p = 0; p < 4; p++) {
                uint32_t b[4];
                ldsm4(b, baseB1[p] + kk * 32);
                mma16816f(acc[0][2 * p],     aA, b[0], b[1]);
                mma16816f(acc[0][2 * p + 1], aA, b[2], b[3]);
                mma16816f(acc[1][2 * p],     aB, b[0], b[1]);
                mma16816f(acc[1][2 * p + 1], aB, b[2], b[3]);
            }
        }

        // sin directly on f32 acc -> f16 A-fragments (no unpack cvts)
        uint32_t ah[2][8][2];
        #pragma unroll
        for (int mt = 0; mt < 2; mt++)
            #pragma unroll
            for (int nt = 0; nt < 8; nt++) {
                ah[mt][nt][0] = pk(__sinf(acc[mt][nt][0]), __sinf(acc[mt][nt][1]));
                ah[mt][nt][1] = pk(__sinf(acc[mt][nt][2]), __sinf(acc[mt][nt][3]));
            }

        // ================= layer 2: f32 accumulators, bias-initialized =================
        float ac2[2][8][4];
        #pragma unroll
        for (int nt = 0; nt < 8; nt++) {
            float bv0 = B2S[nt * 8 + tig * 2];
            float bv1 = B2S[nt * 8 + tig * 2 + 1];
            #pragma unroll
            for (int mt = 0; mt < 2; mt++) {
                ac2[mt][nt][0] = bv0; ac2[mt][nt][1] = bv1;
                ac2[mt][nt][2] = bv0; ac2[mt][nt][3] = bv1;
            }
        }

        #pragma unroll
        for (int kk = 0; kk < 4; kk++) {
            #pragma unroll
            for (int p = 0; p < 4; p++) {
                uint32_t b[4];
                ldsm4(b, baseB2[p] + kk * 32);
                #pragma unroll
                for (int mt = 0; mt < 2; mt++) {
                    uint32_t a[4] = { ah[mt][2 * kk][0], ah[mt][2 * kk][1],
                                      ah[mt][2 * kk + 1][0], ah[mt][2 * kk + 1][1] };
                    mma16816f(ac2[mt][2 * p],     a, b[0], b[1]);
                    mma16816f(ac2[mt][2 * p + 1], a, b[2], b[3]);
                }
            }
        }

        // sin directly on f32 ac2 -> f16 A-fragments for layer 3 (reuse ah)
        #pragma unroll
        for (int mt = 0; mt < 2; mt++)
            #pragma unroll
            for (int nt = 0; nt < 8; nt++) {
                ah[mt][nt][0] = pk(__sinf(ac2[mt][nt][0]), __sinf(ac2[mt][nt][1]));
                ah[mt][nt][1] = pk(__sinf(ac2[mt][nt][2]), __sinf(ac2[mt][nt][3]));
            }

        // ================= layer 3 via MMA (N=8 pad, f32 acc, b3 in init) =================
        #pragma unroll
        for (int mt = 0; mt < 2; mt++) {
            float c[4] = { i3a, i3b, i3a, i3b };
            #pragma unroll
            for (int kk = 0; kk < 4; kk++) {
                uint32_t a[4] = { ah[mt][2 * kk][0], ah[mt][2 * kk][1],
                                  ah[mt][2 * kk + 1][0], ah[mt][2 * kk + 1][1] };
                mma16816f(c, a, B3f[kk][0], B3f[kk][1]);
            }

            // residual bases via shuffle (lane r holds bases of row warpRow+r)
            float bxA = __shfl_sync(0xffffffffu, bx, mt * 16 + g);
            float byA = __shfl_sync(0xffffffffu, by, mt * 16 + g);
            float bzA = __shfl_sync(0xffffffffu, bz, mt * 16 + g);
            float bxB = __shfl_sync(0xffffffffu, bx, mt * 16 + g + 8);
            float byB = __shfl_sync(0xffffffffu, by, mt * 16 + g + 8);
            float bzB = __shfl_sync(0xffffffffu, bz, mt * 16 + g + 8);

            int rA = tile * 128 + warpRow + mt * 16 + g;
            int rB = rA + 8;
            if (tig == 0) {      // C cols 0,1 = out.x, out.y
                out[rA * 3 + 0] = bxA + c[0];
                out[rA * 3 + 1] = byA + c[1];
                out[rB * 3 + 0] = bxB + c[2];
                out[rB * 3 + 1] = byB + c[3];
            } else if (tig == 1) {  // C col 2 = out.z
                out[rA * 3 + 2] = bzA + c[0];
                out[rB * 3 + 2] = bzB + c[2];
            }
        }
        __syncwarp();   // all lanes done reading XS before next tile overwrites
    }
}

extern "C" void kernel_launch(void* const* d_in, const int* in_sizes, int n_in,
                              void* d_out, int out_size) {
    const float* bases   = (const float*)d_in[0];
    const float* normals = (const float*)d_in[1];
    const float* enc     = (const float*)d_in[2];
    const float* W1      = (const float*)d_in[3];
    const float* b1      = (const float*)d_in[4];
    const float* W2      = (const float*)d_in[5];
    const float* b2      = (const float*)d_in[6];
    const float* W3      = (const float*)d_in[7];
    const float* b3      = (const float*)d_in[8];
    float* out = (float*)d_out;

    cudaFuncSetAttribute(fused_encode_mlp,
                         cudaFuncAttributeMaxDynamicSharedMemorySize, SMEM_BYTES);

    // persistent: 148 SMs x 4 CTAs (smem-limited, 16 warps/SM)
    fused_encode_mlp<<<592, 128, SMEM_BYTES>>>(bases, normals, enc,
                                               W1, b1, W2, b2, W3, b3, out);
}